// round 2
// baseline (speedup 1.0000x reference)
#include <cuda_runtime.h>

#define NN 100000
#define EE 3200000
#define ET (EE + NN)

// ---------------- scratch (device globals; no runtime allocation) ----------
__device__ int g_is64;

__device__ __align__(16) float g_h1[NN * 32];     // layer1 transformed features
__device__ float g_asrc1[NN * 2];
__device__ float g_adst1[NN * 2];
__device__ unsigned g_m1[NN * 2];                 // encoded segment max
__device__ float g_s1[NN * 2];                    // segment expsum
__device__ float g_e1[ET * 2];                    // per-edge logits -> exp
__device__ __align__(16) float g_out1[NN * 32];   // layer1 output (pre-relu)
__device__ __align__(16) float g_h2[NN * 40];
__device__ float g_asrc2[NN];
__device__ float g_adst2[NN];
__device__ unsigned g_m2[NN];
__device__ float g_s2[NN];
__device__ float g_e2[ET];

// ---------------- helpers ---------------------------------------------------
__device__ __forceinline__ unsigned fenc(float f) {
    unsigned b = __float_as_uint(f);
    return (b & 0x80000000u) ? ~b : (b | 0x80000000u);
}
__device__ __forceinline__ float fdec(unsigned u) {
    unsigned b = (u & 0x80000000u) ? (u ^ 0x80000000u) : ~u;
    return __uint_as_float(b);
}
__device__ __forceinline__ int edge_at(const void* e, int idx) {
    return g_is64 ? (int)((const long long*)e)[idx] : ((const int*)e)[idx];
}
// sm_90+ vectorized global float reduction (4 adds in one L2 op)
__device__ __forceinline__ void red_add_v4(float4* addr, float4 v) {
    asm volatile("red.global.add.v4.f32 [%0], {%1, %2, %3, %4};"
                 :: "l"(addr), "f"(v.x), "f"(v.y), "f"(v.z), "f"(v.w)
                 : "memory");
}

// ---------------- kernels ---------------------------------------------------
__global__ void k_detect(const void* edges) {
    if (threadIdx.x == 0 && blockIdx.x == 0) {
        const long long* p = (const long long*)edges;
        int ok = 1;
        for (int i = 0; i < 64; i++) {
            long long v = p[i];
            if (v < 0 || v >= NN) { ok = 0; break; }
        }
        g_is64 = ok;
    }
}

__global__ void k_init(float* __restrict__ out, const float* __restrict__ b2) {
    int i = blockIdx.x * blockDim.x + threadIdx.x;
    if (i < NN * 2) { g_m1[i] = 0u; g_s1[i] = 0.f; }
    if (i < NN)     { g_m2[i] = 0u; g_s2[i] = 0.f; }
    if (i < NN * 32) g_out1[i] = 0.f;
    if (i < NN * 40) out[i] = b2[i % 40];
}

// h1 = X @ W1 (128->32), fused a_src1/a_dst1 reductions. 8 nodes / 256-thread block.
__global__ void k_gemm1(const float* __restrict__ X, const float* __restrict__ W1,
                        const float* __restrict__ as1, const float* __restrict__ ad1) {
    __shared__ float Ws[128 * 32];
    __shared__ float Xs[8][128];
    int t = threadIdx.x;
    for (int i = t; i < 128 * 32; i += 256) Ws[i] = W1[i];
    int node0 = blockIdx.x * 8;
    for (int i = t; i < 8 * 128; i += 256) {
        int r = i >> 7, c = i & 127;
        Xs[r][c] = X[(node0 + r) * 128 + c];
    }
    __syncthreads();
    int local = t >> 5, c = t & 31;   // c = lane
    int node = node0 + local;
    float sum = 0.f;
#pragma unroll
    for (int k = 0; k < 128; k++) sum = fmaf(Xs[local][k], Ws[k * 32 + c], sum);
    g_h1[node * 32 + c] = sum;

    int h = c >> 4, cc = c & 15;
    float vs = sum * as1[h * 16 + cc];
    float vd = sum * ad1[h * 16 + cc];
#pragma unroll
    for (int off = 8; off; off >>= 1) {
        vs += __shfl_xor_sync(0xffffffffu, vs, off);
        vd += __shfl_xor_sync(0xffffffffu, vd, off);
    }
    if (cc == 0) { g_asrc1[node * 2 + h] = vs; g_adst1[node * 2 + h] = vd; }
}

// ---- layer1 edge passes (H=2) ----
__global__ void k_edgeA1(const void* edges) {
    int i = blockIdx.x * blockDim.x + threadIdx.x;
    if (i >= ET) return;
    int s, d;
    if (i < EE) { s = edge_at(edges, i); d = edge_at(edges, EE + i); }
    else        { s = d = i - EE; }
#pragma unroll
    for (int h = 0; h < 2; h++) {
        float e = g_asrc1[s * 2 + h] + g_adst1[d * 2 + h];
        e = e > 0.f ? e : 0.2f * e;
        g_e1[i * 2 + h] = e;
        atomicMax(&g_m1[d * 2 + h], fenc(e));
    }
}
__global__ void k_edgeB1(const void* edges) {
    int i = blockIdx.x * blockDim.x + threadIdx.x;
    if (i >= ET) return;
    int d = (i < EE) ? edge_at(edges, EE + i) : i - EE;
#pragma unroll
    for (int h = 0; h < 2; h++) {
        float ex = __expf(g_e1[i * 2 + h] - fdec(g_m1[d * 2 + h]));
        g_e1[i * 2 + h] = ex;
        atomicAdd(&g_s1[d * 2 + h], ex);
    }
}
__global__ void k_edgeC1(const void* edges) {
    int i = blockIdx.x * blockDim.x + threadIdx.x;
    if (i >= ET) return;
    int s, d;
    if (i < EE) { s = edge_at(edges, i); d = edge_at(edges, EE + i); }
    else        { s = d = i - EE; }
    float a0 = g_e1[i * 2 + 0] / (g_s1[d * 2 + 0] + 1e-16f);
    float a1 = g_e1[i * 2 + 1] / (g_s1[d * 2 + 1] + 1e-16f);
    const float4* hp = (const float4*)(g_h1 + s * 32);
    float4* op = (float4*)(g_out1 + d * 32);
#pragma unroll
    for (int q = 0; q < 8; q++) {
        float4 v = hp[q];
        float a = (q < 4) ? a0 : a1;
        v.x *= a; v.y *= a; v.z *= a; v.w *= a;
        red_add_v4(op + q, v);
    }
}

// h2 = relu(out1 + b1) @ W2 (32->40). 8 nodes / 320-thread block.
__global__ void k_gemm2(const float* __restrict__ W2, const float* __restrict__ b1) {
    __shared__ float Ws[32 * 40];
    __shared__ float Xs[8][32];
    int t = threadIdx.x;
    for (int i = t; i < 32 * 40; i += 320) Ws[i] = W2[i];
    int node0 = blockIdx.x * 8;
    for (int i = t; i < 8 * 32; i += 320) {
        int r = i >> 5, c = i & 31;
        float v = g_out1[(node0 + r) * 32 + c] + b1[c];
        Xs[r][c] = v > 0.f ? v : 0.f;
    }
    __syncthreads();
    int local = t / 40, col = t % 40;
    int node = node0 + local;
    float sum = 0.f;
#pragma unroll
    for (int k = 0; k < 32; k++) sum = fmaf(Xs[local][k], Ws[k * 40 + col], sum);
    g_h2[node * 40 + col] = sum;
}

// a_src2/a_dst2: one warp per node over 40 channels.
__global__ void k_a2(const float* __restrict__ as2, const float* __restrict__ ad2) {
    int node = blockIdx.x * 8 + (threadIdx.x >> 5);
    int lane = threadIdx.x & 31;
    if (node >= NN) return;
    const float* row = g_h2 + node * 40;
    float v1 = row[lane];
    float v2 = (lane < 8) ? row[32 + lane] : 0.f;
    float sv = v1 * as2[lane] + ((lane < 8) ? v2 * as2[32 + lane] : 0.f);
    float dv = v1 * ad2[lane] + ((lane < 8) ? v2 * ad2[32 + lane] : 0.f);
#pragma unroll
    for (int off = 16; off; off >>= 1) {
        sv += __shfl_xor_sync(0xffffffffu, sv, off);
        dv += __shfl_xor_sync(0xffffffffu, dv, off);
    }
    if (lane == 0) { g_asrc2[node] = sv; g_adst2[node] = dv; }
}

// ---- layer2 edge passes (H=1, C=40) ----
__global__ void k_edgeA2(const void* edges) {
    int i = blockIdx.x * blockDim.x + threadIdx.x;
    if (i >= ET) return;
    int s, d;
    if (i < EE) { s = edge_at(edges, i); d = edge_at(edges, EE + i); }
    else        { s = d = i - EE; }
    float e = g_asrc2[s] + g_adst2[d];
    e = e > 0.f ? e : 0.2f * e;
    g_e2[i] = e;
    atomicMax(&g_m2[d], fenc(e));
}
__global__ void k_edgeB2(const void* edges) {
    int i = blockIdx.x * blockDim.x + threadIdx.x;
    if (i >= ET) return;
    int d = (i < EE) ? edge_at(edges, EE + i) : i - EE;
    float ex = __expf(g_e2[i] - fdec(g_m2[d]));
    g_e2[i] = ex;
    atomicAdd(&g_s2[d], ex);
}
__global__ void k_edgeC2(const void* edges, float* __restrict__ out) {
    int i = blockIdx.x * blockDim.x + threadIdx.x;
    if (i >= ET) return;
    int s, d;
    if (i < EE) { s = edge_at(edges, i); d = edge_at(edges, EE + i); }
    else        { s = d = i - EE; }
    float a = g_e2[i] / (g_s2[d] + 1e-16f);
    const float4* hp = (const float4*)(g_h2 + s * 40);
    float4* op = (float4*)(out + d * 40);
#pragma unroll
    for (int q = 0; q < 10; q++) {
        float4 v = hp[q];
        v.x *= a; v.y *= a; v.z *= a; v.w *= a;
        red_add_v4(op + q, v);
    }
}

// ---------------- launch ----------------------------------------------------
extern "C" void kernel_launch(void* const* d_in, const int* in_sizes, int n_in,
                              void* d_out, int out_size) {
    const float* X   = (const float*)d_in[0];
    const void*  edges = d_in[1];
    // d_in[2] = weight (ignored, edge_dim=None)
    const float* W1  = (const float*)d_in[3];
    const float* as1 = (const float*)d_in[4];
    const float* ad1 = (const float*)d_in[5];
    const float* b1  = (const float*)d_in[6];
    const float* W2  = (const float*)d_in[7];
    const float* as2 = (const float*)d_in[8];
    const float* ad2 = (const float*)d_in[9];
    const float* b2  = (const float*)d_in[10];
    float* out = (float*)d_out;

    const int EG = (ET + 255) / 256;

    k_detect<<<1, 32>>>(edges);
    k_init<<<(NN * 40 + 255) / 256, 256>>>(out, b2);
    k_gemm1<<<NN / 8, 256>>>(X, W1, as1, ad1);
    k_edgeA1<<<EG, 256>>>(edges);
    k_edgeB1<<<EG, 256>>>(edges);
    k_edgeC1<<<EG, 256>>>(edges);
    k_gemm2<<<NN / 8, 320>>>(W2, b1);
    k_a2<<<(NN + 7) / 8, 256>>>(as2, ad2);
    k_edgeA2<<<EG, 256>>>(edges);
    k_edgeB2<<<EG, 256>>>(edges);
    k_edgeC2<<<EG, 256>>>(edges, out);
}

// round 3
// speedup vs baseline: 1.1577x; 1.1577x over previous
#include <cuda_runtime.h>

#define NN 100000
#define EE 3200000
#define ET (EE + NN)

// ---------------- scratch (device globals; no runtime allocation) ----------
__device__ int g_is64;
__device__ __align__(8)  int2   g_edge[ET];        // decoded (src,dst) incl self-loops
__device__ __align__(16) float  g_h1[NN * 32];     // layer1 transformed features
__device__ __align__(8)  float2 g_a1s[NN];         // (a_src h0, a_src h1)
__device__ __align__(8)  float2 g_a1d[NN];         // (a_dst h0, a_dst h1)
__device__ __align__(8)  float2 g_s1[NN];          // segment expsum per head
__device__ __align__(8)  float2 g_e1[ET];          // per-edge exp(e) per head
__device__ __align__(16) float  g_out1[NN * 32];   // layer1 aggregate (unnormalized)
__device__ __align__(16) float  g_h2[NN * 40];
__device__ float g_a2s[NN];
__device__ float g_a2d[NN];
__device__ float g_s2[NN];
__device__ float g_e2[ET];

// ---------------- helpers ---------------------------------------------------
__device__ __forceinline__ void red_add_v4(float4* addr, float4 v) {
    asm volatile("red.global.add.v4.f32 [%0], {%1, %2, %3, %4};"
                 :: "l"(addr), "f"(v.x), "f"(v.y), "f"(v.z), "f"(v.w)
                 : "memory");
}
__device__ __forceinline__ void red_add_v2(float2* addr, float2 v) {
    asm volatile("red.global.add.v2.f32 [%0], {%1, %2};"
                 :: "l"(addr), "f"(v.x), "f"(v.y)
                 : "memory");
}
__device__ __forceinline__ float lrelu(float e) { return e > 0.f ? e : 0.2f * e; }

// ---------------- kernels ---------------------------------------------------
__global__ void k_detect(const void* edges) {
    if (threadIdx.x == 0 && blockIdx.x == 0) {
        const long long* p = (const long long*)edges;
        int ok = 1;
        for (int i = 0; i < 64; i++) {
            long long v = p[i];
            if (v < 0 || v >= NN) { ok = 0; break; }
        }
        g_is64 = ok;
    }
}

// Decode edge list (either dtype) + append self-loops into int2 array.
__global__ void k_cvt(const void* edges) {
    int i = blockIdx.x * blockDim.x + threadIdx.x;
    if (i >= ET) return;
    int2 e;
    if (i < EE) {
        if (g_is64) {
            const long long* p = (const long long*)edges;
            e.x = (int)p[i]; e.y = (int)p[EE + i];
        } else {
            const int* p = (const int*)edges;
            e.x = p[i]; e.y = p[EE + i];
        }
    } else {
        e.x = e.y = i - EE;
    }
    g_edge[i] = e;
}

__global__ void k_init(float* __restrict__ out) {
    int i = blockIdx.x * blockDim.x + threadIdx.x;
    if (i < NN) { g_s1[i] = make_float2(0.f, 0.f); g_s2[i] = 0.f; }
    if (i < NN * 32) g_out1[i] = 0.f;
    if (i < NN * 40) out[i] = 0.f;
}

// h1 = X @ W1 (128->32), fused a_src1/a_dst1 reductions. 8 nodes / 256-thread block.
__global__ void k_gemm1(const float* __restrict__ X, const float* __restrict__ W1,
                        const float* __restrict__ as1, const float* __restrict__ ad1) {
    __shared__ float Ws[128 * 32];
    __shared__ float Xs[8][128];
    int t = threadIdx.x;
    for (int i = t; i < 128 * 32; i += 256) Ws[i] = W1[i];
    int node0 = blockIdx.x * 8;
    for (int i = t; i < 8 * 128; i += 256) {
        int r = i >> 7, c = i & 127;
        Xs[r][c] = X[(node0 + r) * 128 + c];
    }
    __syncthreads();
    int local = t >> 5, c = t & 31;
    int node = node0 + local;
    float sum = 0.f;
#pragma unroll
    for (int k = 0; k < 128; k++) sum = fmaf(Xs[local][k], Ws[k * 32 + c], sum);
    g_h1[node * 32 + c] = sum;

    int h = c >> 4, cc = c & 15;
    float vs = sum * as1[h * 16 + cc];
    float vd = sum * ad1[h * 16 + cc];
#pragma unroll
    for (int off = 8; off; off >>= 1) {
        vs += __shfl_xor_sync(0xffffffffu, vs, off);
        vd += __shfl_xor_sync(0xffffffffu, vd, off);
    }
    if (cc == 0) {
        ((float*)g_a1s)[node * 2 + h] = vs;
        ((float*)g_a1d)[node * 2 + h] = vd;
    }
}

// ---- layer1: attention (exp + segment-sum fused, no max pass) ----
__global__ void k_att1() {
    int i = blockIdx.x * blockDim.x + threadIdx.x;
    if (i >= ET) return;
    int2 ed = g_edge[i];
    float2 as = g_a1s[ed.x];
    float2 ad = g_a1d[ed.y];
    float ex0 = __expf(lrelu(as.x + ad.x));
    float ex1 = __expf(lrelu(as.y + ad.y));
    g_e1[i] = make_float2(ex0, ex1);
    red_add_v2(&g_s1[ed.y], make_float2(ex0, ex1));
}

// ---- layer1: unnormalized message scatter ----
__global__ void k_msg1() {
    int i = blockIdx.x * blockDim.x + threadIdx.x;
    if (i >= ET) return;
    int2 ed = g_edge[i];
    float2 ex = g_e1[i];
    const float4* hp = (const float4*)(g_h1 + ed.x * 32);
    float4* op = (float4*)(g_out1 + ed.y * 32);
#pragma unroll
    for (int q = 0; q < 8; q++) {
        float4 v = hp[q];
        float a = (q < 4) ? ex.x : ex.y;
        v.x *= a; v.y *= a; v.z *= a; v.w *= a;
        red_add_v4(op + q, v);
    }
}

// h2 = relu(out1/s1 + b1) @ W2 (32->40), fused normalization. 8 nodes / 320 thr.
__global__ void k_gemm2(const float* __restrict__ W2, const float* __restrict__ b1) {
    __shared__ float Ws[32 * 40];
    __shared__ float Xs[8][32];
    int t = threadIdx.x;
    for (int i = t; i < 32 * 40; i += 320) Ws[i] = W2[i];
    int node0 = blockIdx.x * 8;
    for (int i = t; i < 8 * 32; i += 320) {
        int r = i >> 5, c = i & 31;
        float2 s = g_s1[node0 + r];
        float sv = (c < 16) ? s.x : s.y;
        float v = g_out1[(node0 + r) * 32 + c] / (sv + 1e-16f) + b1[c];
        Xs[r][c] = v > 0.f ? v : 0.f;
    }
    __syncthreads();
    int local = t / 40, col = t % 40;
    int node = node0 + local;
    float sum = 0.f;
#pragma unroll
    for (int k = 0; k < 32; k++) sum = fmaf(Xs[local][k], Ws[k * 40 + col], sum);
    g_h2[node * 40 + col] = sum;
}

// a_src2/a_dst2: one warp per node over 40 channels.
__global__ void k_a2(const float* __restrict__ as2, const float* __restrict__ ad2) {
    int node = blockIdx.x * 8 + (threadIdx.x >> 5);
    int lane = threadIdx.x & 31;
    if (node >= NN) return;
    const float* row = g_h2 + node * 40;
    float v1 = row[lane];
    float v2 = (lane < 8) ? row[32 + lane] : 0.f;
    float sv = v1 * as2[lane] + ((lane < 8) ? v2 * as2[32 + lane] : 0.f);
    float dv = v1 * ad2[lane] + ((lane < 8) ? v2 * ad2[32 + lane] : 0.f);
#pragma unroll
    for (int off = 16; off; off >>= 1) {
        sv += __shfl_xor_sync(0xffffffffu, sv, off);
        dv += __shfl_xor_sync(0xffffffffu, dv, off);
    }
    if (lane == 0) { g_a2s[node] = sv; g_a2d[node] = dv; }
}

// ---- layer2: attention ----
__global__ void k_att2() {
    int i = blockIdx.x * blockDim.x + threadIdx.x;
    if (i >= ET) return;
    int2 ed = g_edge[i];
    float ex = __expf(lrelu(g_a2s[ed.x] + g_a2d[ed.y]));
    g_e2[i] = ex;
    atomicAdd(&g_s2[ed.y], ex);   // no return use -> RED
}

// ---- layer2: unnormalized message scatter into d_out ----
__global__ void k_msg2(float* __restrict__ out) {
    int i = blockIdx.x * blockDim.x + threadIdx.x;
    if (i >= ET) return;
    int2 ed = g_edge[i];
    float a = g_e2[i];
    const float4* hp = (const float4*)(g_h2 + ed.x * 40);
    float4* op = (float4*)(out + ed.y * 40);
#pragma unroll
    for (int q = 0; q < 10; q++) {
        float4 v = hp[q];
        v.x *= a; v.y *= a; v.z *= a; v.w *= a;
        red_add_v4(op + q, v);
    }
}

// Final: normalize by s2 and add bias.
__global__ void k_fin(float* __restrict__ out, const float* __restrict__ b2) {
    int i = blockIdx.x * blockDim.x + threadIdx.x;
    if (i >= NN * 40) return;
    int n = i / 40, c = i - n * 40;
    out[i] = out[i] / (g_s2[n] + 1e-16f) + b2[c];
}

// ---------------- launch ----------------------------------------------------
extern "C" void kernel_launch(void* const* d_in, const int* in_sizes, int n_in,
                              void* d_out, int out_size) {
    const float* X   = (const float*)d_in[0];
    const void*  edges = d_in[1];
    const float* W1  = (const float*)d_in[3];
    const float* as1 = (const float*)d_in[4];
    const float* ad1 = (const float*)d_in[5];
    const float* b1  = (const float*)d_in[6];
    const float* W2  = (const float*)d_in[7];
    const float* as2 = (const float*)d_in[8];
    const float* ad2 = (const float*)d_in[9];
    const float* b2  = (const float*)d_in[10];
    float* out = (float*)d_out;

    const int EG = (ET + 255) / 256;

    k_detect<<<1, 32>>>(edges);
    k_init<<<(NN * 40 + 255) / 256, 256>>>(out);
    k_cvt<<<EG, 256>>>(edges);
    k_gemm1<<<NN / 8, 256>>>(X, W1, as1, ad1);
    k_att1<<<EG, 256>>>();
    k_msg1<<<EG, 256>>>();
    k_gemm2<<<NN / 8, 320>>>(W2, b1);
    k_a2<<<(NN + 7) / 8, 256>>>(as2, ad2);
    k_att2<<<EG, 256>>>();
    k_msg2<<<EG, 256>>>(out);
    k_fin<<<(NN * 40 + 255) / 256, 256>>>(out, b2);
}

// round 5
// speedup vs baseline: 1.2460x; 1.0762x over previous
#include <cuda_runtime.h>

#define NN 100000
#define EE 3200000
#define ET (EE + NN)

// ---------------- scratch (device globals; no runtime allocation) ----------
__device__ int g_is64;
__device__ __align__(8)  int2   g_edge[ET];        // decoded (src,dst) incl self-loops
__device__ __align__(16) float  g_h1[NN * 32];     // layer1 transformed features
__device__ __align__(8)  float2 g_a1s[NN];         // (a_src h0, a_src h1)
__device__ __align__(8)  float2 g_a1d[NN];         // (a_dst h0, a_dst h1)
__device__ __align__(8)  float2 g_s1[NN];          // segment expsum per head
__device__ __align__(16) float  g_out1[NN * 32];   // layer1 aggregate (unnormalized)
__device__ __align__(16) float  g_h2[NN * 40];
__device__ float g_a2s[NN];
__device__ float g_a2d[NN];
__device__ float g_s2[NN];

// ---------------- helpers ---------------------------------------------------
__device__ __forceinline__ void red_add_v4(float4* addr, float4 v) {
    asm volatile("red.global.add.v4.f32 [%0], {%1, %2, %3, %4};"
                 :: "l"(addr), "f"(v.x), "f"(v.y), "f"(v.z), "f"(v.w)
                 : "memory");
}
__device__ __forceinline__ void red_add_v2(float2* addr, float2 v) {
    asm volatile("red.global.add.v2.f32 [%0], {%1, %2};"
                 :: "l"(addr), "f"(v.x), "f"(v.y)
                 : "memory");
}
__device__ __forceinline__ float lrelu(float e) { return e > 0.f ? e : 0.2f * e; }

// ---------------- kernels ---------------------------------------------------
__global__ void k_detect(const void* edges) {
    if (threadIdx.x == 0 && blockIdx.x == 0) {
        const long long* p = (const long long*)edges;
        int ok = 1;
        for (int i = 0; i < 64; i++) {
            long long v = p[i];
            if (v < 0 || v >= NN) { ok = 0; break; }
        }
        g_is64 = ok;
    }
}

__global__ void k_init(float* __restrict__ out) {
    int i = blockIdx.x * blockDim.x + threadIdx.x;
    if (i < NN) { g_s1[i] = make_float2(0.f, 0.f); g_s2[i] = 0.f; }
    if (i < NN * 32) g_out1[i] = 0.f;
    if (i < NN * 40) out[i] = 0.f;
}

// h1 = X @ W1 (128->32), register-tiled: 32 nodes/block, thread = (4 nodes x 1 col).
// W transposed in smem (padded) for conflict-free LDS.128; X rows from smem.
__global__ void k_gemm1(const float* __restrict__ X, const float* __restrict__ W1,
                        const float* __restrict__ as1, const float* __restrict__ ad1) {
    __shared__ float Wt[32][132];       // [col][k], +4 pad -> conflict-free float4
    __shared__ float Xs[32][128];       // [node][k]
    int t = threadIdx.x;
    for (int i = t; i < 4096; i += 256) {
        int k = i >> 5, c = i & 31;
        Wt[c][k] = W1[i];
    }
    int node0 = blockIdx.x * 32;
    {
        const float4* Xg = (const float4*)(X + (size_t)node0 * 128);
        float4* Xd = (float4*)&Xs[0][0];
        for (int i = t; i < 1024; i += 256) Xd[i] = Xg[i];
    }
    __syncthreads();

    int c = t & 31, g = t >> 5;          // col, node-group (4 nodes)
    const float4* wrow = (const float4*)&Wt[c][0];
    const float4* x0 = (const float4*)&Xs[g * 4 + 0][0];
    const float4* x1 = (const float4*)&Xs[g * 4 + 1][0];
    const float4* x2 = (const float4*)&Xs[g * 4 + 2][0];
    const float4* x3 = (const float4*)&Xs[g * 4 + 3][0];
    float acc[4] = {0.f, 0.f, 0.f, 0.f};
#pragma unroll 8
    for (int kk = 0; kk < 32; kk++) {
        float4 w = wrow[kk];
        float4 a;
        a = x0[kk]; acc[0] = fmaf(a.x, w.x, fmaf(a.y, w.y, fmaf(a.z, w.z, fmaf(a.w, w.w, acc[0]))));
        a = x1[kk]; acc[1] = fmaf(a.x, w.x, fmaf(a.y, w.y, fmaf(a.z, w.z, fmaf(a.w, w.w, acc[1]))));
        a = x2[kk]; acc[2] = fmaf(a.x, w.x, fmaf(a.y, w.y, fmaf(a.z, w.z, fmaf(a.w, w.w, acc[2]))));
        a = x3[kk]; acc[3] = fmaf(a.x, w.x, fmaf(a.y, w.y, fmaf(a.z, w.z, fmaf(a.w, w.w, acc[3]))));
    }

    float asc = as1[c], adc = ad1[c];   // (2,16) contiguous == linear index c
    int h = c >> 4, cc = c & 15;
#pragma unroll
    for (int j = 0; j < 4; j++) {
        int node = node0 + g * 4 + j;
        g_h1[node * 32 + c] = acc[j];
        float vs = acc[j] * asc;
        float vd = acc[j] * adc;
#pragma unroll
        for (int off = 8; off; off >>= 1) {
            vs += __shfl_xor_sync(0xffffffffu, vs, off);
            vd += __shfl_xor_sync(0xffffffffu, vd, off);
        }
        if (cc == 0) {
            ((float*)g_a1s)[node * 2 + h] = vs;
            ((float*)g_a1d)[node * 2 + h] = vd;
        }
    }
}

// ---- layer1: fused edge decode + attention + message scatter ----
__global__ void k_msg1(const void* edges) {
    int i = blockIdx.x * blockDim.x + threadIdx.x;
    if (i >= ET) return;
    int s, d;
    if (i < EE) {
        if (g_is64) {
            const long long* p = (const long long*)edges;
            s = (int)__ldg(p + i); d = (int)__ldg(p + EE + i);
        } else {
            const int* p = (const int*)edges;
            s = __ldg(p + i); d = __ldg(p + EE + i);
        }
    } else {
        s = d = i - EE;
    }
    g_edge[i] = make_int2(s, d);

    float2 as = __ldg(&g_a1s[s]);
    float2 ad = __ldg(&g_a1d[d]);
    float ex0 = __expf(lrelu(as.x + ad.x));
    float ex1 = __expf(lrelu(as.y + ad.y));
    red_add_v2(&g_s1[d], make_float2(ex0, ex1));

    const float4* hp = (const float4*)(g_h1 + s * 32);
    float4* op = (float4*)(g_out1 + d * 32);
#pragma unroll
    for (int q = 0; q < 8; q++) {
        float4 v = __ldg(hp + q);
        float a = (q < 4) ? ex0 : ex1;
        v.x *= a; v.y *= a; v.z *= a; v.w *= a;
        red_add_v4(op + q, v);
    }
}

// h2 = relu(out1/s1 + b1) @ W2 (32->40), fused normalization. 8 nodes / 320 thr.
__global__ void k_gemm2(const float* __restrict__ W2, const float* __restrict__ b1) {
    __shared__ float Ws[32 * 40];
    __shared__ float Xs[8][32];
    int t = threadIdx.x;
    for (int i = t; i < 32 * 40; i += 320) Ws[i] = W2[i];
    int node0 = blockIdx.x * 8;
    for (int i = t; i < 8 * 32; i += 320) {
        int r = i >> 5, c = i & 31;
        float2 s = g_s1[node0 + r];
        float sv = (c < 16) ? s.x : s.y;
        float v = g_out1[(node0 + r) * 32 + c] / (sv + 1e-16f) + b1[c];
        Xs[r][c] = v > 0.f ? v : 0.f;
    }
    __syncthreads();
    int local = t / 40, col = t % 40;
    int node = node0 + local;
    float sum = 0.f;
#pragma unroll
    for (int k = 0; k < 32; k++) sum = fmaf(Xs[local][k], Ws[k * 40 + col], sum);
    g_h2[node * 40 + col] = sum;
}

// a_src2/a_dst2: one warp per node over 40 channels.
__global__ void k_a2(const float* __restrict__ as2, const float* __restrict__ ad2) {
    int node = blockIdx.x * 8 + (threadIdx.x >> 5);
    int lane = threadIdx.x & 31;
    if (node >= NN) return;
    const float* row = g_h2 + node * 40;
    float v1 = row[lane];
    float v2 = (lane < 8) ? row[32 + lane] : 0.f;
    float sv = v1 * as2[lane] + ((lane < 8) ? v2 * as2[32 + lane] : 0.f);
    float dv = v1 * ad2[lane] + ((lane < 8) ? v2 * ad2[32 + lane] : 0.f);
#pragma unroll
    for (int off = 16; off; off >>= 1) {
        sv += __shfl_xor_sync(0xffffffffu, sv, off);
        dv += __shfl_xor_sync(0xffffffffu, dv, off);
    }
    if (lane == 0) { g_a2s[node] = sv; g_a2d[node] = dv; }
}

// ---- layer2: fused attention + message scatter into d_out. 2 edges/thread. ----
__global__ void k_msg2(float* __restrict__ out) {
    int base = (blockIdx.x * blockDim.x + threadIdx.x) * 2;
#pragma unroll
    for (int u = 0; u < 2; u++) {
        int i = base + u;
        if (i >= ET) return;
        int2 ed = g_edge[i];
        float ex = __expf(lrelu(__ldg(&g_a2s[ed.x]) + __ldg(&g_a2d[ed.y])));
        atomicAdd(&g_s2[ed.y], ex);   // no return use -> RED
        const float4* hp = (const float4*)(g_h2 + ed.x * 40);
        float4* op = (float4*)(out + ed.y * 40);
#pragma unroll
        for (int q = 0; q < 10; q++) {
            float4 v = __ldg(hp + q);
            v.x *= ex; v.y *= ex; v.z *= ex; v.w *= ex;
            red_add_v4(op + q, v);
        }
    }
}

// Final: normalize by s2 and add bias.
__global__ void k_fin(float* __restrict__ out, const float* __restrict__ b2) {
    int i = blockIdx.x * blockDim.x + threadIdx.x;
    if (i >= NN * 40) return;
    int n = i / 40, c = i - n * 40;
    out[i] = out[i] / (g_s2[n] + 1e-16f) + b2[c];
}

// ---------------- launch ----------------------------------------------------
extern "C" void kernel_launch(void* const* d_in, const int* in_sizes, int n_in,
                              void* d_out, int out_size) {
    const float* X   = (const float*)d_in[0];
    const void*  edges = d_in[1];
    const float* W1  = (const float*)d_in[3];
    const float* as1 = (const float*)d_in[4];
    const float* ad1 = (const float*)d_in[5];
    const float* b1  = (const float*)d_in[6];
    const float* W2  = (const float*)d_in[7];
    const float* as2 = (const float*)d_in[8];
    const float* ad2 = (const float*)d_in[9];
    const float* b2  = (const float*)d_in[10];
    float* out = (float*)d_out;

    const int EG = (ET + 255) / 256;
    const int EG2 = (ET + 511) / 512;

    k_detect<<<1, 32>>>(edges);
    k_init<<<(NN * 40 + 255) / 256, 256>>>(out);
    k_gemm1<<<NN / 32, 256>>>(X, W1, as1, ad1);
    k_msg1<<<EG, 256>>>(edges);
    k_gemm2<<<(NN + 7) / 8, 320>>>(W2, b1);
    k_a2<<<(NN + 7) / 8, 256>>>(as2, ad2);
    k_msg2<<<EG2, 256>>>(out);
    k_fin<<<(NN * 40 + 255) / 256, 256>>>(out, b2);
}

// round 6
// speedup vs baseline: 1.9121x; 1.5346x over previous
#include <cuda_runtime.h>

#define NN 100000
#define EE 3200000
#define ET (EE + NN)

// ---------------- scratch (device globals; no runtime allocation) ----------
__device__ int g_is64;
__device__ __align__(8)  int2   g_edge[ET];        // decoded (src,dst) incl self-loops
__device__ __align__(16) float  g_h1[NN * 32];     // layer1 transformed features
__device__ __align__(8)  float2 g_a1s[NN];         // (a_src h0, a_src h1)
__device__ __align__(8)  float2 g_a1d[NN];         // (a_dst h0, a_dst h1)
__device__ __align__(8)  float2 g_s1[NN];          // segment expsum per head
__device__ __align__(16) float  g_out1[NN * 32];   // layer1 aggregate (unnormalized)
__device__ __align__(16) float  g_h2[NN * 40];
__device__ float g_a2s[NN];
__device__ float g_a2d[NN];
__device__ float g_s2[NN];

// ---------------- helpers ---------------------------------------------------
__device__ __forceinline__ void red_add_v4(float4* addr, float4 v) {
    asm volatile("red.global.add.v4.f32 [%0], {%1, %2, %3, %4};"
                 :: "l"(addr), "f"(v.x), "f"(v.y), "f"(v.z), "f"(v.w)
                 : "memory");
}
__device__ __forceinline__ void red_add_v2(float2* addr, float2 v) {
    asm volatile("red.global.add.v2.f32 [%0], {%1, %2};"
                 :: "l"(addr), "f"(v.x), "f"(v.y)
                 : "memory");
}
__device__ __forceinline__ float lrelu(float e) { return e > 0.f ? e : 0.2f * e; }

// ---------------- kernels ---------------------------------------------------
__global__ void k_detect(const void* edges) {
    if (threadIdx.x == 0 && blockIdx.x == 0) {
        const long long* p = (const long long*)edges;
        int ok = 1;
        for (int i = 0; i < 64; i++) {
            long long v = p[i];
            if (v < 0 || v >= NN) { ok = 0; break; }
        }
        g_is64 = ok;
    }
}

__global__ void k_init(float* __restrict__ out) {
    int i = blockIdx.x * blockDim.x + threadIdx.x;
    if (i < NN) { g_s1[i] = make_float2(0.f, 0.f); g_s2[i] = 0.f; }
    if (i < NN * 32) g_out1[i] = 0.f;
    if (i < NN * 40) out[i] = 0.f;
}

// h1 = X @ W1 (128->32), register-tiled: 32 nodes/block, thread = (4 nodes x 1 col).
__global__ void k_gemm1(const float* __restrict__ X, const float* __restrict__ W1,
                        const float* __restrict__ as1, const float* __restrict__ ad1) {
    __shared__ float Wt[32][132];       // [col][k], +4 pad -> conflict-free float4
    __shared__ float Xs[32][128];       // [node][k]
    int t = threadIdx.x;
    for (int i = t; i < 4096; i += 256) {
        int k = i >> 5, c = i & 31;
        Wt[c][k] = W1[i];
    }
    int node0 = blockIdx.x * 32;
    {
        const float4* Xg = (const float4*)(X + (size_t)node0 * 128);
        float4* Xd = (float4*)&Xs[0][0];
        for (int i = t; i < 1024; i += 256) Xd[i] = Xg[i];
    }
    __syncthreads();

    int c = t & 31, g = t >> 5;          // col, node-group (4 nodes)
    const float4* wrow = (const float4*)&Wt[c][0];
    const float4* x0 = (const float4*)&Xs[g * 4 + 0][0];
    const float4* x1 = (const float4*)&Xs[g * 4 + 1][0];
    const float4* x2 = (const float4*)&Xs[g * 4 + 2][0];
    const float4* x3 = (const float4*)&Xs[g * 4 + 3][0];
    float acc[4] = {0.f, 0.f, 0.f, 0.f};
#pragma unroll 8
    for (int kk = 0; kk < 32; kk++) {
        float4 w = wrow[kk];
        float4 a;
        a = x0[kk]; acc[0] = fmaf(a.x, w.x, fmaf(a.y, w.y, fmaf(a.z, w.z, fmaf(a.w, w.w, acc[0]))));
        a = x1[kk]; acc[1] = fmaf(a.x, w.x, fmaf(a.y, w.y, fmaf(a.z, w.z, fmaf(a.w, w.w, acc[1]))));
        a = x2[kk]; acc[2] = fmaf(a.x, w.x, fmaf(a.y, w.y, fmaf(a.z, w.z, fmaf(a.w, w.w, acc[2]))));
        a = x3[kk]; acc[3] = fmaf(a.x, w.x, fmaf(a.y, w.y, fmaf(a.z, w.z, fmaf(a.w, w.w, acc[3]))));
    }

    float asc = as1[c], adc = ad1[c];   // (2,16) contiguous == linear index c
    int h = c >> 4, cc = c & 15;
#pragma unroll
    for (int j = 0; j < 4; j++) {
        int node = node0 + g * 4 + j;
        g_h1[node * 32 + c] = acc[j];
        float vs = acc[j] * asc;
        float vd = acc[j] * adc;
#pragma unroll
        for (int off = 8; off; off >>= 1) {
            vs += __shfl_xor_sync(0xffffffffu, vs, off);
            vd += __shfl_xor_sync(0xffffffffu, vd, off);
        }
        if (cc == 0) {
            ((float*)g_a1s)[node * 2 + h] = vs;
            ((float*)g_a1d)[node * 2 + h] = vd;
        }
    }
}

// ---- layer1: warp-cooperative fused edge pass. 8 lanes per edge. ----
// The 8 lanes cover the edge's 128B h1 row with ONE coalesced LDG.128 / RED.128
// per lane-instruction (4 distinct lines per warp instead of ~32).
__global__ void k_msg1(const void* edges) {
    int tid = blockIdx.x * blockDim.x + threadIdx.x;
    int i = tid >> 3;          // edge index
    int q = tid & 7;           // lane within edge-group
    if (i >= ET) return;
    int s, d;
    if (i < EE) {
        if (g_is64) {
            const long long* p = (const long long*)edges;
            s = (int)__ldg(p + i); d = (int)__ldg(p + EE + i);   // 8-lane broadcast
        } else {
            const int* p = (const int*)edges;
            s = __ldg(p + i); d = __ldg(p + EE + i);
        }
    } else {
        s = d = i - EE;
    }
    if (q == 0) g_edge[i] = make_int2(s, d);

    float2 as = __ldg(&g_a1s[s]);     // broadcast
    float2 ad = __ldg(&g_a1d[d]);     // broadcast
    float ex0 = __expf(lrelu(as.x + ad.x));
    float ex1 = __expf(lrelu(as.y + ad.y));
    if (q == 0) red_add_v2(&g_s1[d], make_float2(ex0, ex1));

    float4 v = __ldg((const float4*)(g_h1 + s * 32) + q);
    float a = (q < 4) ? ex0 : ex1;
    v.x *= a; v.y *= a; v.z *= a; v.w *= a;
    red_add_v4((float4*)(g_out1 + d * 32) + q, v);
}

// h2 = relu(out1/s1 + b1) @ W2 (32->40), fused normalization. 8 nodes / 320 thr.
__global__ void k_gemm2(const float* __restrict__ W2, const float* __restrict__ b1) {
    __shared__ float Ws[32 * 40];
    __shared__ float Xs[8][32];
    int t = threadIdx.x;
    for (int i = t; i < 32 * 40; i += 320) Ws[i] = W2[i];
    int node0 = blockIdx.x * 8;
    for (int i = t; i < 8 * 32; i += 320) {
        int r = i >> 5, c = i & 31;
        float2 s = g_s1[node0 + r];
        float sv = (c < 16) ? s.x : s.y;
        float v = g_out1[(node0 + r) * 32 + c] / (sv + 1e-16f) + b1[c];
        Xs[r][c] = v > 0.f ? v : 0.f;
    }
    __syncthreads();
    int local = t / 40, col = t % 40;
    int node = node0 + local;
    float sum = 0.f;
#pragma unroll
    for (int k = 0; k < 32; k++) sum = fmaf(Xs[local][k], Ws[k * 40 + col], sum);
    g_h2[node * 40 + col] = sum;
}

// a_src2/a_dst2: one warp per node over 40 channels.
__global__ void k_a2(const float* __restrict__ as2, const float* __restrict__ ad2) {
    int node = blockIdx.x * 8 + (threadIdx.x >> 5);
    int lane = threadIdx.x & 31;
    if (node >= NN) return;
    const float* row = g_h2 + node * 40;
    float v1 = row[lane];
    float v2 = (lane < 8) ? row[32 + lane] : 0.f;
    float sv = v1 * as2[lane] + ((lane < 8) ? v2 * as2[32 + lane] : 0.f);
    float dv = v1 * ad2[lane] + ((lane < 8) ? v2 * ad2[32 + lane] : 0.f);
#pragma unroll
    for (int off = 16; off; off >>= 1) {
        sv += __shfl_xor_sync(0xffffffffu, sv, off);
        dv += __shfl_xor_sync(0xffffffffu, dv, off);
    }
    if (lane == 0) { g_a2s[node] = sv; g_a2d[node] = dv; }
}

// ---- layer2: warp-cooperative fused edge pass into d_out. 8 lanes/edge, 160B row. ----
__global__ void k_msg2(float* __restrict__ out) {
    int tid = blockIdx.x * blockDim.x + threadIdx.x;
    int i = tid >> 3;
    int q = tid & 7;
    if (i >= ET) return;
    int2 ed = g_edge[i];            // 8-lane broadcast
    float ex = __expf(lrelu(__ldg(&g_a2s[ed.x]) + __ldg(&g_a2d[ed.y])));
    if (q == 0) atomicAdd(&g_s2[ed.y], ex);   // no return use -> RED

    const float4* hp = (const float4*)(g_h2 + ed.x * 40);
    float4* op = (float4*)(out + ed.y * 40);
    float4 v = __ldg(hp + q);
    v.x *= ex; v.y *= ex; v.z *= ex; v.w *= ex;
    red_add_v4(op + q, v);
    if (q < 2) {
        float4 w = __ldg(hp + 8 + q);
        w.x *= ex; w.y *= ex; w.z *= ex; w.w *= ex;
        red_add_v4(op + 8 + q, w);
    }
}

// Final: normalize by s2 and add bias.
__global__ void k_fin(float* __restrict__ out, const float* __restrict__ b2) {
    int i = blockIdx.x * blockDim.x + threadIdx.x;
    if (i >= NN * 40) return;
    int n = i / 40, c = i - n * 40;
    out[i] = out[i] / (g_s2[n] + 1e-16f) + b2[c];
}

// ---------------- launch ----------------------------------------------------
extern "C" void kernel_launch(void* const* d_in, const int* in_sizes, int n_in,
                              void* d_out, int out_size) {
    const float* X   = (const float*)d_in[0];
    const void*  edges = d_in[1];
    const float* W1  = (const float*)d_in[3];
    const float* as1 = (const float*)d_in[4];
    const float* ad1 = (const float*)d_in[5];
    const float* b1  = (const float*)d_in[6];
    const float* W2  = (const float*)d_in[7];
    const float* as2 = (const float*)d_in[8];
    const float* ad2 = (const float*)d_in[9];
    const float* b2  = (const float*)d_in[10];
    float* out = (float*)d_out;

    const long long TH = (long long)ET * 8;
    const int EGW = (int)((TH + 255) / 256);

    k_detect<<<1, 32>>>(edges);
    k_init<<<(NN * 40 + 255) / 256, 256>>>(out);
    k_gemm1<<<NN / 32, 256>>>(X, W1, as1, ad1);
    k_msg1<<<EGW, 256>>>(edges);
    k_gemm2<<<(NN + 7) / 8, 320>>>(W2, b1);
    k_a2<<<(NN + 7) / 8, 256>>>(as2, ad2);
    k_msg2<<<EGW, 256>>>(out);
    k_fin<<<(NN * 40 + 255) / 256, 256>>>(out, b2);
}